// round 10
// baseline (speedup 1.0000x reference)
#include <cuda_runtime.h>
#include <math.h>

#define FDIM 256
#define BMAX 1024
#define MMAX 500000
#define NMAX 200000
#define CPW  32      // candidates per warp (8 iterations x 4)
#define PREBLK 1024  // blocks doing k_pre work inside k_fused

// Scratch (allocation-free: __device__ globals)
__device__ float    g_groot[BMAX * FDIM];   // per-root x_r * w_ego_root * w_ego_u
__device__ float2   g_rootsc[BMAX];         // {1/max(nr,eps), budgets/200}
__device__ float    g_sv[BMAX];             // x_r . w_layer_v
__device__ unsigned g_pnorm[BMAX];          // encoded float max
__device__ float    g_agg[MMAX];            // segment_sum(sv[edge_src] -> edge_dst)
__device__ float    g_pu[MMAX];             // p_u before normalization
__device__ float4   g_node[NMAX];           // {1/max(nu,eps), su, 0.5*n_imp, 0}

__device__ __forceinline__ unsigned f2key(float f) {
    unsigned u = __float_as_uint(f);
    return (u & 0x80000000u) ? ~u : (u | 0x80000000u);
}
__device__ __forceinline__ float key2f(unsigned k) {
    unsigned u = (k & 0x80000000u) ? (k ^ 0x80000000u) : ~k;
    return __uint_as_float(u);
}
__device__ __forceinline__ float dot4(float4 a, float4 b) {
    return a.x * b.x + a.y * b.y + a.z * b.z + a.w * b.w;
}
__device__ __forceinline__ float sq4(float4 a, float4 w) {
    float t0 = a.x * w.x, t1 = a.y * w.y, t2 = a.z * w.z, t3 = a.w * w.w;
    return t0 * t0 + t1 * t1 + t2 * t2 + t3 * t3;
}

// K1: per-root precompute (one block per root) + zero g_agg (strided).
__global__ void k_root(const float* __restrict__ x,
                       const float* __restrict__ w_ego_root,
                       const float* __restrict__ w_ego_u,
                       const float* __restrict__ w_layer_v,
                       const float* __restrict__ budgets,
                       const int*   __restrict__ batch_nodes,
                       int B, int M)
{
    int b = blockIdx.x;
    int f = threadIdx.x;

    for (int j = b * FDIM + f; j < M; j += gridDim.x * FDIM) g_agg[j] = 0.0f;

    float xr = x[(size_t)batch_nodes[b] * FDIM + f];
    float h  = xr * w_ego_root[f];
    g_groot[b * FDIM + f] = h * w_ego_u[f];
    float s1 = h * h;
    float s2 = xr * w_layer_v[f];

    __shared__ float sh1[8], sh2[8];
    #pragma unroll
    for (int o = 16; o; o >>= 1) {
        s1 += __shfl_xor_sync(0xffffffffu, s1, o);
        s2 += __shfl_xor_sync(0xffffffffu, s2, o);
    }
    int w = f >> 5, l = f & 31;
    if (l == 0) { sh1[w] = s1; sh2[w] = s2; }
    __syncthreads();
    if (f == 0) {
        float t1 = 0.f, t2 = 0.f;
        #pragma unroll
        for (int i = 0; i < 8; i++) { t1 += sh1[i]; t2 += sh2[i]; }
        g_rootsc[b] = make_float2(1.0f / fmaxf(sqrtf(t1), 1e-6f),
                                  budgets[b] * (1.0f / 200.0f));
        g_sv[b] = t2;
        g_pnorm[b] = f2key(-INFINITY);
    }
}

// K2: fused per-node precompute (blocks [0, PREBLK)) + edge scatter-add
// (blocks [PREBLK, ...)). The two halves are independent.
__global__ void __launch_bounds__(256)
k_fused(const float* __restrict__ x,
        const float* __restrict__ w_ego_u,
        const float* __restrict__ w_layer_u,
        const float* __restrict__ n_imp,
        const int* __restrict__ edge_src,
        const int* __restrict__ edge_dst,
        int N, int E)
{
    if (blockIdx.x < PREBLK) {
        // ---- per-node precompute: {invnu, su, 0.5*n_imp} ----
        int lane = threadIdx.x & 31;
        int gw = (blockIdx.x * blockDim.x + threadIdx.x) >> 5;
        int nw = PREBLK * (blockDim.x >> 5);
        const float4* x4 = (const float4*)x;

        float4 wea = __ldg(((const float4*)w_ego_u)   + lane);
        float4 web = __ldg(((const float4*)w_ego_u)   + lane + 32);
        float4 wla = __ldg(((const float4*)w_layer_u) + lane);
        float4 wlb = __ldg(((const float4*)w_layer_u) + lane + 32);

        for (int n = gw * 2; n < N; n += nw * 2) {
            bool two = (n + 1 < N);
            float4 a0 = __ldg(x4 + (size_t)n * 64 + lane);
            float4 b0 = __ldg(x4 + (size_t)n * 64 + lane + 32);
            int n1 = two ? n + 1 : n;
            float4 a1 = __ldg(x4 + (size_t)n1 * 64 + lane);
            float4 b1 = __ldg(x4 + (size_t)n1 * 64 + lane + 32);

            float nu0 = sq4(a0, wea) + sq4(b0, web);
            float su0 = dot4(a0, wla) + dot4(b0, wlb);
            float nu1 = sq4(a1, wea) + sq4(b1, web);
            float su1 = dot4(a1, wla) + dot4(b1, wlb);

            nu0 += __shfl_xor_sync(0xffffffffu, nu0, 16);
            su0 += __shfl_xor_sync(0xffffffffu, su0, 16);
            nu1 += __shfl_xor_sync(0xffffffffu, nu1, 16);
            su1 += __shfl_xor_sync(0xffffffffu, su1, 16);
            bool hi16 = (lane & 16) != 0;
            float v0 = hi16 ? su0 : nu0;      // lanes<16: nu, >=16: su
            float v1 = hi16 ? su1 : nu1;
            #pragma unroll
            for (int o = 8; o; o >>= 1) {
                v0 += __shfl_xor_sync(0xffffffffu, v0, o);
                v1 += __shfl_xor_sync(0xffffffffu, v1, o);
            }
            float su0f = __shfl_sync(0xffffffffu, v0, 16);
            float su1f = __shfl_sync(0xffffffffu, v1, 16);
            if (lane == 0) {
                g_node[n] = make_float4(1.0f / fmaxf(sqrtf(v0), 1e-6f), su0f,
                                        0.5f * __ldg(n_imp + n), 0.0f);
                if (two)
                    g_node[n1] = make_float4(1.0f / fmaxf(sqrtf(v1), 1e-6f), su1f,
                                             0.5f * __ldg(n_imp + n1), 0.0f);
            }
        }
    } else {
        // ---- edge scatter-add: 4 edges per thread ----
        int i = ((blockIdx.x - PREBLK) * blockDim.x + threadIdx.x) * 4;
        if (i + 3 < E) {
            int4 s = *(const int4*)(edge_src + i);
            int4 d = *(const int4*)(edge_dst + i);
            atomicAdd(&g_agg[d.x], g_sv[s.x]);
            atomicAdd(&g_agg[d.y], g_sv[s.y]);
            atomicAdd(&g_agg[d.z], g_sv[s.z]);
            atomicAdd(&g_agg[d.w], g_sv[s.w]);
        } else {
            for (int j = i; j < E; j++)
                atomicAdd(&g_agg[edge_dst[j]], g_sv[edge_src[j]]);
        }
    }
}

// K4: dot-only candidate kernel. 8-lanes-per-candidate, 4 candidates/warp
// iteration. g row cached in REGISTERS across iterations (sorted batch_ptr),
// x loads are the only L1tex traffic in steady state.
__global__ void __launch_bounds__(256)
k_cand(const float* __restrict__ x,
       const int* __restrict__ u_ids,
       const int* __restrict__ batch_ptr, int M)
{
    int lane  = threadIdx.x & 31;
    int gwarp = (blockIdx.x * blockDim.x + threadIdx.x) >> 5;
    int c = lane >> 3;          // candidate slot 0..3
    int s = lane & 7;           // sublane 0..7

    const float4* x4 = (const float4*)x;
    const float4* g4 = (const float4*)g_groot;

    int Mmain = M & ~3;

    // tail: warp 0 handles [Mmain, M) with a 32-lane dot-only path
    if (gwarp == 0 && Mmain < M) {
        for (int m = Mmain; m < M; m++) {
            int u = __ldg(u_ids + m);
            int b = __ldg(batch_ptr + m);
            float4 xa = __ldg(x4 + (size_t)u * 64 + lane);
            float4 xb = __ldg(x4 + (size_t)u * 64 + lane + 32);
            float4 ta = __ldg(g4 + (size_t)b * 64 + lane);
            float4 tb = __ldg(g4 + (size_t)b * 64 + lane + 32);
            float d = dot4(xa, ta) + dot4(xb, tb);
            #pragma unroll
            for (int o = 16; o; o >>= 1)
                d += __shfl_xor_sync(0xffffffffu, d, o);
            if (lane == 0) {
                float4 nd = __ldg((const float4*)g_node + u);
                float2 rs = __ldg(g_rootsc + b);
                float p = (d * rs.x * nd.x + tanhf(g_agg[m] + nd.y)) * nd.z * rs.y;
                g_pu[m] = p;
                atomicMax(&g_pnorm[b], f2key(p));
            }
        }
    }

    int base = gwarp * CPW;
    if (base >= Mmain) return;
    int lim = base + CPW; if (lim > Mmain) lim = Mmain;

    int bcache = -1;
    float4 g0, g1, g2, g3, g4r, g5, g6, g7;
    g0 = g1 = g2 = g3 = g4r = g5 = g6 = g7 = make_float4(0.f, 0.f, 0.f, 0.f);

    for (int m0 = base; m0 < lim; m0 += 4) {
        int4 uu = *(const int4*)(u_ids + m0);
        int4 bb = *(const int4*)(batch_ptr + m0);
        int u = (c == 0) ? uu.x : (c == 1) ? uu.y : (c == 2) ? uu.z : uu.w;
        int b = (c == 0) ? bb.x : (c == 1) ? bb.y : (c == 2) ? bb.z : bb.w;

        // 8 independent wide loads per lane — 4KB in flight per warp
        const float4* xr = x4 + (size_t)u * 64 + s;
        float4 xv0 = __ldg(xr);
        float4 xv1 = __ldg(xr + 8);
        float4 xv2 = __ldg(xr + 16);
        float4 xv3 = __ldg(xr + 24);
        float4 xv4 = __ldg(xr + 32);
        float4 xv5 = __ldg(xr + 40);
        float4 xv6 = __ldg(xr + 48);
        float4 xv7 = __ldg(xr + 56);

        // finalize scalars, hoisted & unguarded (group-uniform addresses)
        float4 nd = __ldg((const float4*)g_node + u);  // {invnu, su, hni}
        float2 rs = __ldg(g_rootsc + b);               // {invnr, bf}
        float  ag = __ldg(g_agg + m0 + c);

        // g row register cache: reload only when batch changes (warp-uniform)
        bool uni = (bb.x == bb.w);
        if (!(uni && bb.x == bcache)) {
            const float4* gr = g4 + (size_t)b * 64 + s;   // per-group b
            g0  = __ldg(gr);
            g1  = __ldg(gr + 8);
            g2  = __ldg(gr + 16);
            g3  = __ldg(gr + 24);
            g4r = __ldg(gr + 32);
            g5  = __ldg(gr + 40);
            g6  = __ldg(gr + 48);
            g7  = __ldg(gr + 56);
            bcache = uni ? bb.x : -1;
        }

        float dot = dot4(xv0, g0)  + dot4(xv1, g1) + dot4(xv2, g2)
                  + dot4(xv3, g3)  + dot4(xv4, g4r) + dot4(xv5, g5)
                  + dot4(xv6, g6)  + dot4(xv7, g7);

        // 3-round reduction within each 8-lane group
        #pragma unroll
        for (int o = 4; o; o >>= 1)
            dot += __shfl_xor_sync(0xffffffffu, dot, o);

        // finalize on ALL lanes (group-uniform values)
        float p = (dot * rs.x * nd.x + tanhf(ag + nd.y)) * nd.z * rs.y;
        unsigned key = f2key(p);

        if (s == 0) g_pu[m0 + c] = p;   // 4 lanes, contiguous 16B

        if (uni) {                      // merge 4 keys -> 1 atomic
            unsigned k1 = key, t;
            t = __shfl_xor_sync(0xffffffffu, k1, 8);  k1 = k1 > t ? k1 : t;
            t = __shfl_xor_sync(0xffffffffu, k1, 16); k1 = k1 > t ? k1 : t;
            if (lane == 0) atomicMax(&g_pnorm[bb.x], k1);
        } else {
            if (s == 0) atomicMax(&g_pnorm[b], key);
        }
    }
}

// K5: normalize + nan/inf replace + clip (vectorized)
__global__ void k_final(const int* __restrict__ batch_ptr,
                        float* __restrict__ out, int M)
{
    int m = (blockIdx.x * blockDim.x + threadIdx.x) * 4;
    if (m + 3 < M) {
        int4   bp = *(const int4*)(batch_ptr + m);
        float4 pu = *(const float4*)(g_pu + m);
        float4 r;
        {
            float p = pu.x / key2f(g_pnorm[bp.x]) + 1.0f;
            if (isnan(p)) p = 0.0f; else if (isinf(p)) p = 1.0f;
            r.x = fminf(fmaxf(p, 1e-5f), 1.0f);
        }
        {
            float p = pu.y / key2f(g_pnorm[bp.y]) + 1.0f;
            if (isnan(p)) p = 0.0f; else if (isinf(p)) p = 1.0f;
            r.y = fminf(fmaxf(p, 1e-5f), 1.0f);
        }
        {
            float p = pu.z / key2f(g_pnorm[bp.z]) + 1.0f;
            if (isnan(p)) p = 0.0f; else if (isinf(p)) p = 1.0f;
            r.z = fminf(fmaxf(p, 1e-5f), 1.0f);
        }
        {
            float p = pu.w / key2f(g_pnorm[bp.w]) + 1.0f;
            if (isnan(p)) p = 0.0f; else if (isinf(p)) p = 1.0f;
            r.w = fminf(fmaxf(p, 1e-5f), 1.0f);
        }
        *(float4*)(out + m) = r;
    } else {
        for (int j = m; j < M; j++) {
            float p = g_pu[j] / key2f(g_pnorm[batch_ptr[j]]) + 1.0f;
            if (isnan(p)) p = 0.0f; else if (isinf(p)) p = 1.0f;
            out[j] = fminf(fmaxf(p, 1e-5f), 1.0f);
        }
    }
}

extern "C" void kernel_launch(void* const* d_in, const int* in_sizes, int n_in,
                              void* d_out, int out_size)
{
    const float* x           = (const float*)d_in[0];
    const float* w_ego_root  = (const float*)d_in[1];
    const float* w_ego_u     = (const float*)d_in[2];
    const float* w_layer_v   = (const float*)d_in[3];
    const float* w_layer_u   = (const float*)d_in[4];
    const float* n_imp       = (const float*)d_in[5];
    const float* budgets     = (const float*)d_in[6];
    const int*   batch_nodes = (const int*)d_in[7];
    const int*   u_ids       = (const int*)d_in[8];
    const int*   batch_ptr   = (const int*)d_in[9];
    const int*   edge_src    = (const int*)d_in[10];
    const int*   edge_dst    = (const int*)d_in[11];
    float* out = (float*)d_out;

    int B = in_sizes[7];
    int M = in_sizes[8];
    int E = in_sizes[10];
    int N = in_sizes[0] / FDIM;

    k_root<<<B, FDIM>>>(x, w_ego_root, w_ego_u, w_layer_v, budgets,
                        batch_nodes, B, M);

    int edgeBlocks = (E / 4 + 255) / 256;
    k_fused<<<PREBLK + edgeBlocks, 256>>>(x, w_ego_u, w_layer_u, n_imp,
                                          edge_src, edge_dst, N, E);

    int Mmain = M & ~3;
    int nwarps = (Mmain + CPW - 1) / CPW;
    int nblocks = (nwarps + 7) / 8;
    if (nblocks < 1) nblocks = 1;
    k_cand<<<nblocks, 256>>>(x, u_ids, batch_ptr, M);

    k_final<<<(M / 4 + 255) / 256, 256>>>(batch_ptr, out, M);
}

// round 11
// speedup vs baseline: 1.1307x; 1.1307x over previous
#include <cuda_runtime.h>
#include <math.h>

#define FDIM 256
#define BMAX 1024
#define MMAX 500000
#define NMAX 200000
#define CPW  32      // candidates per warp (8 iterations x 4)
#define PREBLK 1024  // blocks doing per-node precompute inside k_fused

// Scratch (allocation-free: __device__ globals)
__device__ float    g_groot[BMAX * FDIM];   // per-root x_r * w_ego_root * w_ego_u
__device__ float2   g_rootsc[BMAX];         // {1/max(nr,eps), budgets/200}
__device__ float    g_sv[BMAX];             // x_r . w_layer_v
__device__ unsigned g_pnorm[BMAX];          // encoded float max
__device__ float    g_agg[MMAX];            // segment_sum(sv[edge_src] -> edge_dst)
__device__ float    g_pu[MMAX];             // p_u before normalization
__device__ float4   g_node[NMAX];           // {1/max(nu,eps), su, 0.5*n_imp, 0}

__device__ __forceinline__ unsigned f2key(float f) {
    unsigned u = __float_as_uint(f);
    return (u & 0x80000000u) ? ~u : (u | 0x80000000u);
}
__device__ __forceinline__ float key2f(unsigned k) {
    unsigned u = (k & 0x80000000u) ? (k ^ 0x80000000u) : ~k;
    return __uint_as_float(u);
}
__device__ __forceinline__ float dot4(float4 a, float4 b) {
    return a.x * b.x + a.y * b.y + a.z * b.z + a.w * b.w;
}
__device__ __forceinline__ float sq4(float4 a, float4 w) {
    float t0 = a.x * w.x, t1 = a.y * w.y, t2 = a.z * w.z, t3 = a.w * w.w;
    return t0 * t0 + t1 * t1 + t2 * t2 + t3 * t3;
}

// K1: per-root precompute (one block per root) + zero g_agg (strided).
__global__ void k_root(const float* __restrict__ x,
                       const float* __restrict__ w_ego_root,
                       const float* __restrict__ w_ego_u,
                       const float* __restrict__ w_layer_v,
                       const float* __restrict__ budgets,
                       const int*   __restrict__ batch_nodes,
                       int B, int M)
{
    int b = blockIdx.x;
    int f = threadIdx.x;

    for (int j = b * FDIM + f; j < M; j += gridDim.x * FDIM) g_agg[j] = 0.0f;

    float xr = x[(size_t)batch_nodes[b] * FDIM + f];
    float h  = xr * w_ego_root[f];
    g_groot[b * FDIM + f] = h * w_ego_u[f];
    float s1 = h * h;
    float s2 = xr * w_layer_v[f];

    __shared__ float sh1[8], sh2[8];
    #pragma unroll
    for (int o = 16; o; o >>= 1) {
        s1 += __shfl_xor_sync(0xffffffffu, s1, o);
        s2 += __shfl_xor_sync(0xffffffffu, s2, o);
    }
    int w = f >> 5, l = f & 31;
    if (l == 0) { sh1[w] = s1; sh2[w] = s2; }
    __syncthreads();
    if (f == 0) {
        float t1 = 0.f, t2 = 0.f;
        #pragma unroll
        for (int i = 0; i < 8; i++) { t1 += sh1[i]; t2 += sh2[i]; }
        g_rootsc[b] = make_float2(1.0f / fmaxf(sqrtf(t1), 1e-6f),
                                  budgets[b] * (1.0f / 200.0f));
        g_sv[b] = t2;
        g_pnorm[b] = f2key(-INFINITY);
    }
}

// K2: fused per-node precompute (blocks [0, PREBLK)) + edge scatter-add
// (blocks [PREBLK, ...)). The two halves are independent.
__global__ void __launch_bounds__(256)
k_fused(const float* __restrict__ x,
        const float* __restrict__ w_ego_u,
        const float* __restrict__ w_layer_u,
        const float* __restrict__ n_imp,
        const int* __restrict__ edge_src,
        const int* __restrict__ edge_dst,
        int N, int E)
{
    if (blockIdx.x < PREBLK) {
        // ---- per-node precompute: {invnu, su, 0.5*n_imp} ----
        int lane = threadIdx.x & 31;
        int gw = (blockIdx.x * blockDim.x + threadIdx.x) >> 5;
        int nw = PREBLK * (blockDim.x >> 5);
        const float4* x4 = (const float4*)x;

        float4 wea = __ldg(((const float4*)w_ego_u)   + lane);
        float4 web = __ldg(((const float4*)w_ego_u)   + lane + 32);
        float4 wla = __ldg(((const float4*)w_layer_u) + lane);
        float4 wlb = __ldg(((const float4*)w_layer_u) + lane + 32);

        for (int n = gw * 2; n < N; n += nw * 2) {
            bool two = (n + 1 < N);
            float4 a0 = __ldg(x4 + (size_t)n * 64 + lane);
            float4 b0 = __ldg(x4 + (size_t)n * 64 + lane + 32);
            int n1 = two ? n + 1 : n;
            float4 a1 = __ldg(x4 + (size_t)n1 * 64 + lane);
            float4 b1 = __ldg(x4 + (size_t)n1 * 64 + lane + 32);

            float nu0 = sq4(a0, wea) + sq4(b0, web);
            float su0 = dot4(a0, wla) + dot4(b0, wlb);
            float nu1 = sq4(a1, wea) + sq4(b1, web);
            float su1 = dot4(a1, wla) + dot4(b1, wlb);

            nu0 += __shfl_xor_sync(0xffffffffu, nu0, 16);
            su0 += __shfl_xor_sync(0xffffffffu, su0, 16);
            nu1 += __shfl_xor_sync(0xffffffffu, nu1, 16);
            su1 += __shfl_xor_sync(0xffffffffu, su1, 16);
            bool hi16 = (lane & 16) != 0;
            float v0 = hi16 ? su0 : nu0;      // lanes<16: nu, >=16: su
            float v1 = hi16 ? su1 : nu1;
            #pragma unroll
            for (int o = 8; o; o >>= 1) {
                v0 += __shfl_xor_sync(0xffffffffu, v0, o);
                v1 += __shfl_xor_sync(0xffffffffu, v1, o);
            }
            float su0f = __shfl_sync(0xffffffffu, v0, 16);
            float su1f = __shfl_sync(0xffffffffu, v1, 16);
            if (lane == 0) {
                g_node[n] = make_float4(1.0f / fmaxf(sqrtf(v0), 1e-6f), su0f,
                                        0.5f * __ldg(n_imp + n), 0.0f);
                if (two)
                    g_node[n1] = make_float4(1.0f / fmaxf(sqrtf(v1), 1e-6f), su1f,
                                             0.5f * __ldg(n_imp + n1), 0.0f);
            }
        }
    } else {
        // ---- edge scatter-add: 4 edges per thread ----
        int i = ((blockIdx.x - PREBLK) * blockDim.x + threadIdx.x) * 4;
        if (i + 3 < E) {
            int4 s = *(const int4*)(edge_src + i);
            int4 d = *(const int4*)(edge_dst + i);
            atomicAdd(&g_agg[d.x], g_sv[s.x]);
            atomicAdd(&g_agg[d.y], g_sv[s.y]);
            atomicAdd(&g_agg[d.z], g_sv[s.z]);
            atomicAdd(&g_agg[d.w], g_sv[s.w]);
        } else {
            for (int j = i; j < E; j++)
                atomicAdd(&g_agg[edge_dst[j]], g_sv[edge_src[j]]);
        }
    }
}

// K4: dot-only candidate kernel. 8-lanes-per-candidate, 4 candidates/warp
// iteration. x loads batched up-front (4KB in flight per warp); g row loaded
// inline via __ldg (L1-hot: all warps on the SM share the same root row).
__global__ void __launch_bounds__(256)
k_cand(const float* __restrict__ x,
       const int* __restrict__ u_ids,
       const int* __restrict__ batch_ptr, int M)
{
    int lane  = threadIdx.x & 31;
    int gwarp = (blockIdx.x * blockDim.x + threadIdx.x) >> 5;
    int c = lane >> 3;          // candidate slot 0..3
    int s = lane & 7;           // sublane 0..7

    const float4* x4 = (const float4*)x;
    const float4* g4 = (const float4*)g_groot;

    int Mmain = M & ~3;

    // tail: warp 0 handles [Mmain, M) with a 32-lane dot-only path
    if (gwarp == 0 && Mmain < M) {
        for (int m = Mmain; m < M; m++) {
            int u = __ldg(u_ids + m);
            int b = __ldg(batch_ptr + m);
            float4 xa = __ldg(x4 + (size_t)u * 64 + lane);
            float4 xb = __ldg(x4 + (size_t)u * 64 + lane + 32);
            float4 ta = __ldg(g4 + (size_t)b * 64 + lane);
            float4 tb = __ldg(g4 + (size_t)b * 64 + lane + 32);
            float d = dot4(xa, ta) + dot4(xb, tb);
            #pragma unroll
            for (int o = 16; o; o >>= 1)
                d += __shfl_xor_sync(0xffffffffu, d, o);
            if (lane == 0) {
                float4 nd = __ldg((const float4*)g_node + u);
                float2 rs = __ldg(g_rootsc + b);
                float p = (d * rs.x * nd.x + tanhf(g_agg[m] + nd.y)) * nd.z * rs.y;
                g_pu[m] = p;
                atomicMax(&g_pnorm[b], f2key(p));
            }
        }
    }

    int base = gwarp * CPW;
    if (base >= Mmain) return;
    int lim = base + CPW; if (lim > Mmain) lim = Mmain;

    for (int m0 = base; m0 < lim; m0 += 4) {
        int4 uu = *(const int4*)(u_ids + m0);
        int4 bb = *(const int4*)(batch_ptr + m0);
        int u = (c == 0) ? uu.x : (c == 1) ? uu.y : (c == 2) ? uu.z : uu.w;
        int b = (c == 0) ? bb.x : (c == 1) ? bb.y : (c == 2) ? bb.z : bb.w;

        // 8 independent wide loads per lane — 4KB in flight per warp
        const float4* xr = x4 + (size_t)u * 64 + s;
        float4 xv0 = __ldg(xr);
        float4 xv1 = __ldg(xr + 8);
        float4 xv2 = __ldg(xr + 16);
        float4 xv3 = __ldg(xr + 24);
        float4 xv4 = __ldg(xr + 32);
        float4 xv5 = __ldg(xr + 40);
        float4 xv6 = __ldg(xr + 48);
        float4 xv7 = __ldg(xr + 56);

        // finalize scalars, hoisted & unguarded (group-uniform addresses)
        float4 nd = __ldg((const float4*)g_node + u);  // {invnu, su, hni}
        float2 rs = __ldg(g_rootsc + b);               // {invnr, bf}
        float  ag = __ldg(g_agg + m0 + c);

        // g row inline (L1-hot — same row for all warps on this SM)
        const float4* gr = g4 + (size_t)b * 64 + s;
        float dot = dot4(xv0, __ldg(gr))
                  + dot4(xv1, __ldg(gr + 8))
                  + dot4(xv2, __ldg(gr + 16))
                  + dot4(xv3, __ldg(gr + 24))
                  + dot4(xv4, __ldg(gr + 32))
                  + dot4(xv5, __ldg(gr + 40))
                  + dot4(xv6, __ldg(gr + 48))
                  + dot4(xv7, __ldg(gr + 56));

        // 3-round reduction within each 8-lane group
        #pragma unroll
        for (int o = 4; o; o >>= 1)
            dot += __shfl_xor_sync(0xffffffffu, dot, o);

        // finalize on ALL lanes (group-uniform values)
        float p = (dot * rs.x * nd.x + tanhf(ag + nd.y)) * nd.z * rs.y;
        unsigned key = f2key(p);

        if (s == 0) g_pu[m0 + c] = p;   // 4 lanes, contiguous 16B

        if (bb.x == bb.w) {             // sorted => all four equal
            unsigned k1 = key, t;
            t = __shfl_xor_sync(0xffffffffu, k1, 8);  k1 = k1 > t ? k1 : t;
            t = __shfl_xor_sync(0xffffffffu, k1, 16); k1 = k1 > t ? k1 : t;
            if (lane == 0) atomicMax(&g_pnorm[bb.x], k1);
        } else {
            if (s == 0) atomicMax(&g_pnorm[b], key);
        }
    }
}

// K5: normalize + nan/inf replace + clip (vectorized)
__global__ void k_final(const int* __restrict__ batch_ptr,
                        float* __restrict__ out, int M)
{
    int m = (blockIdx.x * blockDim.x + threadIdx.x) * 4;
    if (m + 3 < M) {
        int4   bp = *(const int4*)(batch_ptr + m);
        float4 pu = *(const float4*)(g_pu + m);
        float4 r;
        {
            float p = pu.x / key2f(g_pnorm[bp.x]) + 1.0f;
            if (isnan(p)) p = 0.0f; else if (isinf(p)) p = 1.0f;
            r.x = fminf(fmaxf(p, 1e-5f), 1.0f);
        }
        {
            float p = pu.y / key2f(g_pnorm[bp.y]) + 1.0f;
            if (isnan(p)) p = 0.0f; else if (isinf(p)) p = 1.0f;
            r.y = fminf(fmaxf(p, 1e-5f), 1.0f);
        }
        {
            float p = pu.z / key2f(g_pnorm[bp.z]) + 1.0f;
            if (isnan(p)) p = 0.0f; else if (isinf(p)) p = 1.0f;
            r.z = fminf(fmaxf(p, 1e-5f), 1.0f);
        }
        {
            float p = pu.w / key2f(g_pnorm[bp.w]) + 1.0f;
            if (isnan(p)) p = 0.0f; else if (isinf(p)) p = 1.0f;
            r.w = fminf(fmaxf(p, 1e-5f), 1.0f);
        }
        *(float4*)(out + m) = r;
    } else {
        for (int j = m; j < M; j++) {
            float p = g_pu[j] / key2f(g_pnorm[batch_ptr[j]]) + 1.0f;
            if (isnan(p)) p = 0.0f; else if (isinf(p)) p = 1.0f;
            out[j] = fminf(fmaxf(p, 1e-5f), 1.0f);
        }
    }
}

extern "C" void kernel_launch(void* const* d_in, const int* in_sizes, int n_in,
                              void* d_out, int out_size)
{
    const float* x           = (const float*)d_in[0];
    const float* w_ego_root  = (const float*)d_in[1];
    const float* w_ego_u     = (const float*)d_in[2];
    const float* w_layer_v   = (const float*)d_in[3];
    const float* w_layer_u   = (const float*)d_in[4];
    const float* n_imp       = (const float*)d_in[5];
    const float* budgets     = (const float*)d_in[6];
    const int*   batch_nodes = (const int*)d_in[7];
    const int*   u_ids       = (const int*)d_in[8];
    const int*   batch_ptr   = (const int*)d_in[9];
    const int*   edge_src    = (const int*)d_in[10];
    const int*   edge_dst    = (const int*)d_in[11];
    float* out = (float*)d_out;

    int B = in_sizes[7];
    int M = in_sizes[8];
    int E = in_sizes[10];
    int N = in_sizes[0] / FDIM;

    k_root<<<B, FDIM>>>(x, w_ego_root, w_ego_u, w_layer_v, budgets,
                        batch_nodes, B, M);

    int edgeBlocks = (E / 4 + 255) / 256;
    k_fused<<<PREBLK + edgeBlocks, 256>>>(x, w_ego_u, w_layer_u, n_imp,
                                          edge_src, edge_dst, N, E);

    int Mmain = M & ~3;
    int nwarps = (Mmain + CPW - 1) / CPW;
    int nblocks = (nwarps + 7) / 8;
    if (nblocks < 1) nblocks = 1;
    k_cand<<<nblocks, 256>>>(x, u_ids, batch_ptr, M);

    k_final<<<(M / 4 + 255) / 256, 256>>>(batch_ptr, out, M);
}

// round 12
// speedup vs baseline: 1.4982x; 1.3251x over previous
#include <cuda_runtime.h>
#include <math.h>

#define FDIM 256
#define BMAX 1024
#define MMAX 500000
#define NMAX 200000
#define CPW  32      // candidates per dot-warp (8 iterations x 4)
#define PREBLK 1024  // blocks doing per-node precompute inside k_fused

// Scratch (allocation-free: __device__ globals)
__device__ float    g_groot[BMAX * FDIM];   // per-root x_r * w_ego_root * w_ego_u
__device__ float2   g_rootsc[BMAX];         // {1/max(nr,eps), budgets/200}
__device__ float    g_sv[BMAX];             // x_r . w_layer_v
__device__ unsigned g_pnorm[BMAX];          // encoded float max
__device__ float    g_agg[MMAX];            // segment_sum(sv[edge_src] -> edge_dst)
__device__ float    g_dot[MMAX];            // raw dot(x_u, g_b)
__device__ float    g_pu[MMAX];             // p_u before normalization
__device__ float4   g_node[NMAX];           // {1/max(nu,eps), su, 0.5*n_imp, 0}

__device__ __forceinline__ unsigned f2key(float f) {
    unsigned u = __float_as_uint(f);
    return (u & 0x80000000u) ? ~u : (u | 0x80000000u);
}
__device__ __forceinline__ float key2f(unsigned k) {
    unsigned u = (k & 0x80000000u) ? (k ^ 0x80000000u) : ~k;
    return __uint_as_float(u);
}
__device__ __forceinline__ float dot4(float4 a, float4 b) {
    return a.x * b.x + a.y * b.y + a.z * b.z + a.w * b.w;
}
__device__ __forceinline__ float sq4(float4 a, float4 w) {
    float t0 = a.x * w.x, t1 = a.y * w.y, t2 = a.z * w.z, t3 = a.w * w.w;
    return t0 * t0 + t1 * t1 + t2 * t2 + t3 * t3;
}

// K1: per-root precompute (one block per root) + zero g_agg (strided).
__global__ void k_root(const float* __restrict__ x,
                       const float* __restrict__ w_ego_root,
                       const float* __restrict__ w_ego_u,
                       const float* __restrict__ w_layer_v,
                       const float* __restrict__ budgets,
                       const int*   __restrict__ batch_nodes,
                       int B, int M)
{
    int b = blockIdx.x;
    int f = threadIdx.x;

    for (int j = b * FDIM + f; j < M; j += gridDim.x * FDIM) g_agg[j] = 0.0f;

    float xr = x[(size_t)batch_nodes[b] * FDIM + f];
    float h  = xr * w_ego_root[f];
    g_groot[b * FDIM + f] = h * w_ego_u[f];
    float s1 = h * h;
    float s2 = xr * w_layer_v[f];

    __shared__ float sh1[8], sh2[8];
    #pragma unroll
    for (int o = 16; o; o >>= 1) {
        s1 += __shfl_xor_sync(0xffffffffu, s1, o);
        s2 += __shfl_xor_sync(0xffffffffu, s2, o);
    }
    int w = f >> 5, l = f & 31;
    if (l == 0) { sh1[w] = s1; sh2[w] = s2; }
    __syncthreads();
    if (f == 0) {
        float t1 = 0.f, t2 = 0.f;
        #pragma unroll
        for (int i = 0; i < 8; i++) { t1 += sh1[i]; t2 += sh2[i]; }
        g_rootsc[b] = make_float2(1.0f / fmaxf(sqrtf(t1), 1e-6f),
                                  budgets[b] * (1.0f / 200.0f));
        g_sv[b] = t2;
        g_pnorm[b] = f2key(-INFINITY);
    }
}

// K2: one kernel, three independent block groups running concurrently:
//   [0, nDotBlk)                    candidate dot gather (the long pole)
//   [nDotBlk, nDotBlk+PREBLK)       per-node {invnu, su, n_imp} precompute
//   [nDotBlk+PREBLK, ...)           edge scatter-add
__global__ void __launch_bounds__(256)
k_fused(const float* __restrict__ x,
        const float* __restrict__ w_ego_u,
        const float* __restrict__ w_layer_u,
        const float* __restrict__ n_imp,
        const int* __restrict__ edge_src,
        const int* __restrict__ edge_dst,
        const int* __restrict__ u_ids,
        const int* __restrict__ batch_ptr,
        int N, int E, int M, int nDotBlk)
{
    const float4* x4 = (const float4*)x;

    if (blockIdx.x < nDotBlk) {
        // ---- candidate dots: 8-lanes-per-candidate, 4 cands/warp-iter ----
        int lane  = threadIdx.x & 31;
        int gwarp = blockIdx.x * 8 + (threadIdx.x >> 5);
        int c = lane >> 3;          // candidate slot 0..3
        int s = lane & 7;           // sublane 0..7
        const float4* g4 = (const float4*)g_groot;

        int Mmain = M & ~3;

        // tail: grid-warp 0 handles [Mmain, M) with a 32-lane path
        if (gwarp == 0 && Mmain < M) {
            for (int m = Mmain; m < M; m++) {
                int u = __ldg(u_ids + m);
                int b = __ldg(batch_ptr + m);
                float4 xa = __ldg(x4 + (size_t)u * 64 + lane);
                float4 xb = __ldg(x4 + (size_t)u * 64 + lane + 32);
                float4 ta = __ldg(g4 + (size_t)b * 64 + lane);
                float4 tb = __ldg(g4 + (size_t)b * 64 + lane + 32);
                float d = dot4(xa, ta) + dot4(xb, tb);
                #pragma unroll
                for (int o = 16; o; o >>= 1)
                    d += __shfl_xor_sync(0xffffffffu, d, o);
                if (lane == 0) g_dot[m] = d;
            }
        }

        int base = gwarp * CPW;
        if (base >= Mmain) return;
        int lim = base + CPW; if (lim > Mmain) lim = Mmain;

        for (int m0 = base; m0 < lim; m0 += 4) {
            int4 uu = *(const int4*)(u_ids + m0);
            int4 bb = *(const int4*)(batch_ptr + m0);
            int u = (c == 0) ? uu.x : (c == 1) ? uu.y : (c == 2) ? uu.z : uu.w;
            int b = (c == 0) ? bb.x : (c == 1) ? bb.y : (c == 2) ? bb.z : bb.w;

            const float4* xr = x4 + (size_t)u * 64 + s;
            float4 xv0 = __ldg(xr);
            float4 xv1 = __ldg(xr + 8);
            float4 xv2 = __ldg(xr + 16);
            float4 xv3 = __ldg(xr + 24);
            float4 xv4 = __ldg(xr + 32);
            float4 xv5 = __ldg(xr + 40);
            float4 xv6 = __ldg(xr + 48);
            float4 xv7 = __ldg(xr + 56);

            const float4* gr = g4 + (size_t)b * 64 + s;
            float dot = dot4(xv0, __ldg(gr))
                      + dot4(xv1, __ldg(gr + 8))
                      + dot4(xv2, __ldg(gr + 16))
                      + dot4(xv3, __ldg(gr + 24))
                      + dot4(xv4, __ldg(gr + 32))
                      + dot4(xv5, __ldg(gr + 40))
                      + dot4(xv6, __ldg(gr + 48))
                      + dot4(xv7, __ldg(gr + 56));

            #pragma unroll
            for (int o = 4; o; o >>= 1)
                dot += __shfl_xor_sync(0xffffffffu, dot, o);

            if (s == 0) g_dot[m0 + c] = dot;   // 4 lanes, 16B coalesced
        }
    } else if (blockIdx.x < nDotBlk + PREBLK) {
        // ---- per-node precompute: {invnu, su, 0.5*n_imp} ----
        int lane = threadIdx.x & 31;
        int gw = (blockIdx.x - nDotBlk) * 8 + (threadIdx.x >> 5);
        int nw = PREBLK * 8;

        float4 wea = __ldg(((const float4*)w_ego_u)   + lane);
        float4 web = __ldg(((const float4*)w_ego_u)   + lane + 32);
        float4 wla = __ldg(((const float4*)w_layer_u) + lane);
        float4 wlb = __ldg(((const float4*)w_layer_u) + lane + 32);

        for (int n = gw * 2; n < N; n += nw * 2) {
            bool two = (n + 1 < N);
            float4 a0 = __ldg(x4 + (size_t)n * 64 + lane);
            float4 b0 = __ldg(x4 + (size_t)n * 64 + lane + 32);
            int n1 = two ? n + 1 : n;
            float4 a1 = __ldg(x4 + (size_t)n1 * 64 + lane);
            float4 b1 = __ldg(x4 + (size_t)n1 * 64 + lane + 32);

            float nu0 = sq4(a0, wea) + sq4(b0, web);
            float su0 = dot4(a0, wla) + dot4(b0, wlb);
            float nu1 = sq4(a1, wea) + sq4(b1, web);
            float su1 = dot4(a1, wla) + dot4(b1, wlb);

            nu0 += __shfl_xor_sync(0xffffffffu, nu0, 16);
            su0 += __shfl_xor_sync(0xffffffffu, su0, 16);
            nu1 += __shfl_xor_sync(0xffffffffu, nu1, 16);
            su1 += __shfl_xor_sync(0xffffffffu, su1, 16);
            bool hi16 = (lane & 16) != 0;
            float v0 = hi16 ? su0 : nu0;      // lanes<16: nu, >=16: su
            float v1 = hi16 ? su1 : nu1;
            #pragma unroll
            for (int o = 8; o; o >>= 1) {
                v0 += __shfl_xor_sync(0xffffffffu, v0, o);
                v1 += __shfl_xor_sync(0xffffffffu, v1, o);
            }
            float su0f = __shfl_sync(0xffffffffu, v0, 16);
            float su1f = __shfl_sync(0xffffffffu, v1, 16);
            if (lane == 0) {
                g_node[n] = make_float4(1.0f / fmaxf(sqrtf(v0), 1e-6f), su0f,
                                        0.5f * __ldg(n_imp + n), 0.0f);
                if (two)
                    g_node[n1] = make_float4(1.0f / fmaxf(sqrtf(v1), 1e-6f), su1f,
                                             0.5f * __ldg(n_imp + n1), 0.0f);
            }
        }
    } else {
        // ---- edge scatter-add: 4 edges per thread ----
        int i = ((blockIdx.x - nDotBlk - PREBLK) * blockDim.x + threadIdx.x) * 4;
        if (i + 3 < E) {
            int4 s = *(const int4*)(edge_src + i);
            int4 d = *(const int4*)(edge_dst + i);
            atomicAdd(&g_agg[d.x], g_sv[s.x]);
            atomicAdd(&g_agg[d.y], g_sv[s.y]);
            atomicAdd(&g_agg[d.z], g_sv[s.z]);
            atomicAdd(&g_agg[d.w], g_sv[s.w]);
        } else {
            for (int j = i; j < E; j++)
                atomicAdd(&g_agg[edge_dst[j]], g_sv[edge_src[j]]);
        }
    }
}

// K3: finalize — p_u from dot/agg/node tables + per-batch max (warp-merged).
__global__ void __launch_bounds__(256)
k_fin1(const int* __restrict__ u_ids,
       const int* __restrict__ batch_ptr, int M)
{
    int idx = blockIdx.x * blockDim.x + threadIdx.x;
    int m = idx * 4;
    if (m + 3 < M) {
        int4   uu = *(const int4*)(u_ids + m);
        int4   bb = *(const int4*)(batch_ptr + m);
        float4 dt = *(const float4*)(g_dot + m);
        float4 ag = *(const float4*)(g_agg + m);

        float4 nd0 = __ldg((const float4*)g_node + uu.x);
        float4 nd1 = __ldg((const float4*)g_node + uu.y);
        float4 nd2 = __ldg((const float4*)g_node + uu.z);
        float4 nd3 = __ldg((const float4*)g_node + uu.w);
        float2 rs0 = __ldg(g_rootsc + bb.x);
        float2 rs1 = __ldg(g_rootsc + bb.y);
        float2 rs2 = __ldg(g_rootsc + bb.z);
        float2 rs3 = __ldg(g_rootsc + bb.w);

        float4 r;
        r.x = (dt.x * rs0.x * nd0.x + tanhf(ag.x + nd0.y)) * nd0.z * rs0.y;
        r.y = (dt.y * rs1.x * nd1.x + tanhf(ag.y + nd1.y)) * nd1.z * rs1.y;
        r.z = (dt.z * rs2.x * nd2.x + tanhf(ag.z + nd2.y)) * nd2.z * rs2.y;
        r.w = (dt.w * rs3.x * nd3.x + tanhf(ag.w + nd3.y)) * nd3.z * rs3.y;
        *(float4*)(g_pu + m) = r;

        unsigned kx = f2key(r.x), ky = f2key(r.y);
        unsigned kz = f2key(r.z), kw = f2key(r.w);
        bool uni4 = (bb.x == bb.w);
        unsigned kmax = kx > ky ? kx : ky;
        kmax = kmax > kz ? kmax : kz;
        kmax = kmax > kw ? kmax : kw;

        unsigned bFirst = __shfl_sync(0xffffffffu, (unsigned)bb.x, 0);
        bool warpUni = __all_sync(0xffffffffu, uni4 && (unsigned)bb.x == bFirst);
        if (warpUni) {
            #pragma unroll
            for (int o = 16; o; o >>= 1) {
                unsigned t = __shfl_xor_sync(0xffffffffu, kmax, o);
                kmax = kmax > t ? kmax : t;
            }
            if ((threadIdx.x & 31) == 0) atomicMax(&g_pnorm[bb.x], kmax);
        } else if (uni4) {
            atomicMax(&g_pnorm[bb.x], kmax);
        } else {
            atomicMax(&g_pnorm[bb.x], kx);
            atomicMax(&g_pnorm[bb.y], ky);
            atomicMax(&g_pnorm[bb.z], kz);
            atomicMax(&g_pnorm[bb.w], kw);
        }
    } else {
        // keep all lanes alive for shuffles above; tail is scalar
        for (int j = m; j < M; j++) {
            int u = __ldg(u_ids + j);
            int b = __ldg(batch_ptr + j);
            float4 nd = __ldg((const float4*)g_node + u);
            float2 rs = __ldg(g_rootsc + b);
            float p = (g_dot[j] * rs.x * nd.x + tanhf(g_agg[j] + nd.y))
                      * nd.z * rs.y;
            g_pu[j] = p;
            atomicMax(&g_pnorm[b], f2key(p));
        }
        unsigned dummy = 0;
        __shfl_sync(0xffffffffu, dummy, 0);   // keep warp convergent w/ main path? (no-op)
    }
}

// K5: normalize + nan/inf replace + clip (vectorized)
__global__ void k_final(const int* __restrict__ batch_ptr,
                        float* __restrict__ out, int M)
{
    int m = (blockIdx.x * blockDim.x + threadIdx.x) * 4;
    if (m + 3 < M) {
        int4   bp = *(const int4*)(batch_ptr + m);
        float4 pu = *(const float4*)(g_pu + m);
        float4 r;
        {
            float p = pu.x / key2f(g_pnorm[bp.x]) + 1.0f;
            if (isnan(p)) p = 0.0f; else if (isinf(p)) p = 1.0f;
            r.x = fminf(fmaxf(p, 1e-5f), 1.0f);
        }
        {
            float p = pu.y / key2f(g_pnorm[bp.y]) + 1.0f;
            if (isnan(p)) p = 0.0f; else if (isinf(p)) p = 1.0f;
            r.y = fminf(fmaxf(p, 1e-5f), 1.0f);
        }
        {
            float p = pu.z / key2f(g_pnorm[bp.z]) + 1.0f;
            if (isnan(p)) p = 0.0f; else if (isinf(p)) p = 1.0f;
            r.z = fminf(fmaxf(p, 1e-5f), 1.0f);
        }
        {
            float p = pu.w / key2f(g_pnorm[bp.w]) + 1.0f;
            if (isnan(p)) p = 0.0f; else if (isinf(p)) p = 1.0f;
            r.w = fminf(fmaxf(p, 1e-5f), 1.0f);
        }
        *(float4*)(out + m) = r;
    } else {
        for (int j = m; j < M; j++) {
            float p = g_pu[j] / key2f(g_pnorm[batch_ptr[j]]) + 1.0f;
            if (isnan(p)) p = 0.0f; else if (isinf(p)) p = 1.0f;
            out[j] = fminf(fmaxf(p, 1e-5f), 1.0f);
        }
    }
}

extern "C" void kernel_launch(void* const* d_in, const int* in_sizes, int n_in,
                              void* d_out, int out_size)
{
    const float* x           = (const float*)d_in[0];
    const float* w_ego_root  = (const float*)d_in[1];
    const float* w_ego_u     = (const float*)d_in[2];
    const float* w_layer_v   = (const float*)d_in[3];
    const float* w_layer_u   = (const float*)d_in[4];
    const float* n_imp       = (const float*)d_in[5];
    const float* budgets     = (const float*)d_in[6];
    const int*   batch_nodes = (const int*)d_in[7];
    const int*   u_ids       = (const int*)d_in[8];
    const int*   batch_ptr   = (const int*)d_in[9];
    const int*   edge_src    = (const int*)d_in[10];
    const int*   edge_dst    = (const int*)d_in[11];
    float* out = (float*)d_out;

    int B = in_sizes[7];
    int M = in_sizes[8];
    int E = in_sizes[10];
    int N = in_sizes[0] / FDIM;

    k_root<<<B, FDIM>>>(x, w_ego_root, w_ego_u, w_layer_v, budgets,
                        batch_nodes, B, M);

    int Mmain = M & ~3;
    int nDotWarps = (Mmain + CPW - 1) / CPW;
    int nDotBlk = (nDotWarps + 7) / 8;
    if (nDotBlk < 1) nDotBlk = 1;
    int edgeBlocks = (E / 4 + 255) / 256;
    k_fused<<<nDotBlk + PREBLK + edgeBlocks, 256>>>(
        x, w_ego_u, w_layer_u, n_imp, edge_src, edge_dst,
        u_ids, batch_ptr, N, E, M, nDotBlk);

    k_fin1<<<(M / 4 + 255) / 256, 256>>>(u_ids, batch_ptr, M);

    k_final<<<(M / 4 + 255) / 256, 256>>>(batch_ptr, out, M);
}